// round 2
// baseline (speedup 1.0000x reference)
#include <cuda_runtime.h>

// Problem constants
#define B_DIM 8
#define S_DIM 1024
#define C_DIM 1024
#define H_NUM 16
#define HD    64

// Scratch (allocation-free rule: __device__ globals)
// g_kv layout: [B, S, 2*C]  — first C = "k" projection (qkv slice 1, which is ALSO q),
//                              second C = "v" projection (qkv slice 2)
__device__ float g_kv [(size_t)B_DIM * S_DIM * 2 * C_DIM];
// g_att layout: [B, S, C] with feature index = h*HD + d (matches transpose+reshape in ref)
__device__ float g_att[(size_t)B_DIM * S_DIM * C_DIM];

// ---------------------------------------------------------------------------
// SGEMM: C[M,N] = A[M,K] @ B[K,N] + bias[N]
// 128x128 tile, BK=16, 256 threads, 8x8 per thread (split 4+4 rows/cols).
// Double-buffered smem: prefetch tile k+1 into registers during compute of
// tile k, one __syncthreads per k-step.
// All dims are multiples of 128/16 here, so no bounds checks.
// ---------------------------------------------------------------------------
#define GT 128
#define GK 16

__global__ __launch_bounds__(256)
void sgemm_bias(const float* __restrict__ A, int lda,
                const float* __restrict__ B, int ldb,
                const float* __restrict__ bias,
                float* __restrict__ Cout, int ldc,
                int K)
{
    __shared__ float As[2][GK][GT + 4];
    __shared__ float Bs[2][GK][GT + 4];

    const int bm = blockIdx.y * GT;
    const int bn = blockIdx.x * GT;
    const int tid = threadIdx.x;
    const int tr = tid >> 4;        // 0..15
    const int tc = tid & 15;        // 0..15

    const int ra = tid >> 2;        // 0..63 (A tile row)
    const int ca = (tid & 3) * 4;   // 0,4,8,12 (A tile k-col)
    const int rb = tid >> 5;        // 0..7  (B tile k-row)
    const int cb = (tid & 31) * 4;  // 0..124 (B tile col)

    const float* Aptr0 = A + (size_t)(bm + ra)      * lda + ca;
    const float* Aptr1 = A + (size_t)(bm + ra + 64) * lda + ca;
    const float* Bptr0 = B + (size_t)rb       * ldb + bn + cb;
    const float* Bptr1 = B + (size_t)(rb + 8) * ldb + bn + cb;

    float acc[8][8];
#pragma unroll
    for (int i = 0; i < 8; i++)
#pragma unroll
        for (int j = 0; j < 8; j++) acc[i][j] = 0.f;

    // ---- preload tile 0 into buffer 0 ----
    {
        float4 a0 = *(const float4*)(Aptr0);
        float4 a1 = *(const float4*)(Aptr1);
        float4 b0 = *(const float4*)(Bptr0);
        float4 b1 = *(const float4*)(Bptr1);
        As[0][ca + 0][ra] = a0.x; As[0][ca + 1][ra] = a0.y;
        As[0][ca + 2][ra] = a0.z; As[0][ca + 3][ra] = a0.w;
        As[0][ca + 0][ra + 64] = a1.x; As[0][ca + 1][ra + 64] = a1.y;
        As[0][ca + 2][ra + 64] = a1.z; As[0][ca + 3][ra + 64] = a1.w;
        *(float4*)&Bs[0][rb][cb]     = b0;
        *(float4*)&Bs[0][rb + 8][cb] = b1;
    }
    __syncthreads();

    int cur = 0;
    for (int k0 = 0; k0 < K; k0 += GK) {
        const int nxt = cur ^ 1;
        const bool more = (k0 + GK) < K;

        // ---- prefetch next tile into registers (LDGs issue before FMA loop) ----
        float4 a0, a1, b0, b1;
        if (more) {
            a0 = *(const float4*)(Aptr0 + k0 + GK);
            a1 = *(const float4*)(Aptr1 + k0 + GK);
            b0 = *(const float4*)(Bptr0 + (size_t)(k0 + GK) * ldb);
            b1 = *(const float4*)(Bptr1 + (size_t)(k0 + GK) * ldb);
        }

        // ---- compute on current buffer ----
#pragma unroll
        for (int kk = 0; kk < GK; kk++) {
            float ar[8], br[8];
            *(float4*)&ar[0] = *(const float4*)&As[cur][kk][tr * 4];
            *(float4*)&ar[4] = *(const float4*)&As[cur][kk][tr * 4 + 64];
            *(float4*)&br[0] = *(const float4*)&Bs[cur][kk][tc * 4];
            *(float4*)&br[4] = *(const float4*)&Bs[cur][kk][tc * 4 + 64];
#pragma unroll
            for (int i = 0; i < 8; i++)
#pragma unroll
                for (int j = 0; j < 8; j++)
                    acc[i][j] = fmaf(ar[i], br[j], acc[i][j]);
        }

        // ---- store prefetched tile into the alternate buffer ----
        if (more) {
            As[nxt][ca + 0][ra] = a0.x; As[nxt][ca + 1][ra] = a0.y;
            As[nxt][ca + 2][ra] = a0.z; As[nxt][ca + 3][ra] = a0.w;
            As[nxt][ca + 0][ra + 64] = a1.x; As[nxt][ca + 1][ra + 64] = a1.y;
            As[nxt][ca + 2][ra + 64] = a1.z; As[nxt][ca + 3][ra + 64] = a1.w;
            *(float4*)&Bs[nxt][rb][cb]     = b0;
            *(float4*)&Bs[nxt][rb + 8][cb] = b1;
        }
        __syncthreads();
        cur = nxt;
    }

    // Epilogue with bias
#pragma unroll
    for (int ih = 0; ih < 2; ih++) {
#pragma unroll
        for (int i = 0; i < 4; i++) {
            const int r = bm + tr * 4 + ih * 64 + i;
#pragma unroll
            for (int jh = 0; jh < 2; jh++) {
                const int c = bn + tc * 4 + jh * 64;
                float4 o;
                o.x = acc[ih * 4 + i][jh * 4 + 0] + bias[c + 0];
                o.y = acc[ih * 4 + i][jh * 4 + 1] + bias[c + 1];
                o.z = acc[ih * 4 + i][jh * 4 + 2] + bias[c + 2];
                o.w = acc[ih * 4 + i][jh * 4 + 3] + bias[c + 3];
                *(float4*)(Cout + (size_t)r * ldc + c) = o;
            }
        }
    }
}

// ---------------------------------------------------------------------------
// Flash attention (fp32, causal, q == k).
// Block: 128 q-rows of one (b,h); 256 threads = 8 warps, each warp owns 16 rows.
// Lane (r = lane/8, c = lane%8): 4 q-rows (rowb..rowb+3) x 8 k-cols (colb..colb+7).
// Q,K stored transposed [d][s] in smem for conflict-free float4 outer-product loads.
// ---------------------------------------------------------------------------
#define FBM 128
#define FBN 64
#define QT_STRIDE (FBM + 4)   // 132
#define KT_STRIDE (FBN + 4)   // 68
#define PS_STRIDE (FBN + 2)   // 66

#define FLASH_SMEM_FLOATS (HD * QT_STRIDE + HD * KT_STRIDE + FBN * HD + FBM * PS_STRIDE)

__global__ __launch_bounds__(256)
void flash_attn(const float* __restrict__ kv, float* __restrict__ att)
{
    extern __shared__ float sm[];
    float* Qt = sm;                          // [HD][QT_STRIDE]
    float* Kt = Qt + HD * QT_STRIDE;         // [HD][KT_STRIDE]
    float* Vs = Kt + HD * KT_STRIDE;         // [FBN][HD]
    float* Ps = Vs + FBN * HD;               // [FBM][PS_STRIDE]

    const int qt = blockIdx.x;               // q tile: 0..7
    const int bh = blockIdx.y;               // 0..127
    const int b = bh >> 4, h = bh & 15;
    const int tid = threadIdx.x;
    const int w = tid >> 5, lane = tid & 31;
    const int r = lane >> 3, c = lane & 7;
    const int rowb = w * 16 + r * 4;         // local q-row base (0..124)
    const int colb = c * 8;                  // local k-col base (0..56)

    const int qbase = qt * FBM;
    const size_t kvrow = 2 * C_DIM;
    const size_t kvbase = (size_t)b * S_DIM * kvrow + (size_t)h * HD;

    // ---- load Q tile transposed: Qt[d][s] ----
    for (int f = tid; f < FBM * (HD / 4); f += 256) {
        const int s  = f >> 4;
        const int d4 = (f & 15) * 4;
        float4 v = *(const float4*)(kv + kvbase + (size_t)(qbase + s) * kvrow + d4);
        Qt[(d4 + 0) * QT_STRIDE + s] = v.x;
        Qt[(d4 + 1) * QT_STRIDE + s] = v.y;
        Qt[(d4 + 2) * QT_STRIDE + s] = v.z;
        Qt[(d4 + 3) * QT_STRIDE + s] = v.w;
    }

    float m_i[4], l_i[4], outAcc[4][8];
#pragma unroll
    for (int i = 0; i < 4; i++) {
        m_i[i] = -1e30f; l_i[i] = 0.f;
#pragma unroll
        for (int j = 0; j < 8; j++) outAcc[i][j] = 0.f;
    }

    const float scale = 0.125f;  // 1/sqrt(64)
    const int ntiles = 2 * qt + 2;

    for (int kt = 0; kt < ntiles; kt++) {
        __syncthreads();
        // ---- load K tile (transposed) + V tile ----
        for (int f = tid; f < FBN * (HD / 4); f += 256) {
            const int s  = f >> 4;
            const int d4 = (f & 15) * 4;
            const float* src = kv + kvbase + (size_t)(kt * FBN + s) * kvrow;
            float4 kk = *(const float4*)(src + d4);
            Kt[(d4 + 0) * KT_STRIDE + s] = kk.x;
            Kt[(d4 + 1) * KT_STRIDE + s] = kk.y;
            Kt[(d4 + 2) * KT_STRIDE + s] = kk.z;
            Kt[(d4 + 3) * KT_STRIDE + s] = kk.w;
            float4 vv = *(const float4*)(src + C_DIM + d4);
            *(float4*)&Vs[s * HD + d4] = vv;
        }
        __syncthreads();

        // ---- QK^T: 4x8 score micro-tile per lane ----
        float sc[4][8];
#pragma unroll
        for (int i = 0; i < 4; i++)
#pragma unroll
            for (int j = 0; j < 8; j++) sc[i][j] = 0.f;

#pragma unroll 4
        for (int d = 0; d < HD; d += 4) {
#pragma unroll
            for (int t = 0; t < 4; t++) {
                float4 qv = *(const float4*)&Qt[(d + t) * QT_STRIDE + rowb];
                float4 k0 = *(const float4*)&Kt[(d + t) * KT_STRIDE + colb];
                float4 k1 = *(const float4*)&Kt[(d + t) * KT_STRIDE + colb + 4];
                float qa[4] = {qv.x, qv.y, qv.z, qv.w};
                float kb[8] = {k0.x, k0.y, k0.z, k0.w, k1.x, k1.y, k1.z, k1.w};
#pragma unroll
                for (int i = 0; i < 4; i++)
#pragma unroll
                    for (int j = 0; j < 8; j++)
                        sc[i][j] = fmaf(qa[i], kb[j], sc[i][j]);
            }
        }

        // ---- scale + causal mask (only last two tiles can cross the diagonal) ----
        const bool domask = (kt >= 2 * qt);
        const int gcol0 = kt * FBN + colb;
#pragma unroll
        for (int i = 0; i < 4; i++) {
            const int grow = qbase + rowb + i;
#pragma unroll
            for (int j = 0; j < 8; j++) {
                float v = sc[i][j] * scale;
                if (domask && (gcol0 + j > grow)) v = -1e30f;
                sc[i][j] = v;
            }
        }

        // ---- online softmax ----
        float mt[4];
#pragma unroll
        for (int i = 0; i < 4; i++) {
            float m = sc[i][0];
#pragma unroll
            for (int j = 1; j < 8; j++) m = fmaxf(m, sc[i][j]);
            m = fmaxf(m, __shfl_xor_sync(0xffffffffu, m, 1));
            m = fmaxf(m, __shfl_xor_sync(0xffffffffu, m, 2));
            m = fmaxf(m, __shfl_xor_sync(0xffffffffu, m, 4));
            mt[i] = m;
        }
        float alpha[4], rs[4];
#pragma unroll
        for (int i = 0; i < 4; i++) {
            const float mn = fmaxf(m_i[i], mt[i]);
            alpha[i] = __expf(m_i[i] - mn);
            m_i[i] = mn;
            float s = 0.f;
#pragma unroll
            for (int j = 0; j < 8; j++) {
                const float p = __expf(sc[i][j] - mn);
                sc[i][j] = p;
                s += p;
            }
            s += __shfl_xor_sync(0xffffffffu, s, 1);
            s += __shfl_xor_sync(0xffffffffu, s, 2);
            s += __shfl_xor_sync(0xffffffffu, s, 4);
            rs[i] = s;
        }
#pragma unroll
        for (int i = 0; i < 4; i++) {
            l_i[i] = l_i[i] * alpha[i] + rs[i];
#pragma unroll
            for (int j = 0; j < 8; j++) outAcc[i][j] *= alpha[i];
        }

        // ---- write P to smem (per-warp region), then P @ V ----
#pragma unroll
        for (int i = 0; i < 4; i++)
#pragma unroll
            for (int j = 0; j < 8; j++)
                Ps[(rowb + i) * PS_STRIDE + colb + j] = sc[i][j];
        __syncwarp();

#pragma unroll 4
        for (int j = 0; j < FBN; j++) {
            float pv[4];
#pragma unroll
            for (int i = 0; i < 4; i++) pv[i] = Ps[(rowb + i) * PS_STRIDE + j];
            float4 v0 = *(const float4*)&Vs[j * HD + colb];
            float4 v1 = *(const float4*)&Vs[j * HD + colb + 4];
            float vb[8] = {v0.x, v0.y, v0.z, v0.w, v1.x, v1.y, v1.z, v1.w};
#pragma unroll
            for (int i = 0; i < 4; i++)
#pragma unroll
                for (int jj = 0; jj < 8; jj++)
                    outAcc[i][jj] = fmaf(pv[i], vb[jj], outAcc[i][jj]);
        }
        __syncwarp();
    }

    // ---- finalize: divide by l, write att[b, s, h*HD + col] ----
#pragma unroll
    for (int i = 0; i < 4; i++) {
        const float inv = 1.0f / l_i[i];
        const size_t obase = ((size_t)b * S_DIM + qbase + rowb + i) * C_DIM
                           + (size_t)h * HD + colb;
        float4 o0, o1;
        o0.x = outAcc[i][0] * inv; o0.y = outAcc[i][1] * inv;
        o0.z = outAcc[i][2] * inv; o0.w = outAcc[i][3] * inv;
        o1.x = outAcc[i][4] * inv; o1.y = outAcc[i][5] * inv;
        o1.z = outAcc[i][6] * inv; o1.w = outAcc[i][7] * inv;
        *(float4*)(att + obase)     = o0;
        *(float4*)(att + obase + 4) = o1;
    }
}

// ---------------------------------------------------------------------------
// Launch
// ---------------------------------------------------------------------------
extern "C" void kernel_launch(void* const* d_in, const int* in_sizes, int n_in,
                              void* d_out, int out_size)
{
    (void)in_sizes; (void)n_in; (void)out_size;
    const float* x     = (const float*)d_in[0];   // [8,1024,1024]
    const float* Wqkv  = (const float*)d_in[1];   // [1024,3072]
    const float* bqkv  = (const float*)d_in[2];   // [3072]
    const float* Wproj = (const float*)d_in[3];   // [1024,1024]
    const float* bproj = (const float*)d_in[4];   // [1024]
    float* out = (float*)d_out;                   // [8,1024,1024]

    float* kv;  cudaGetSymbolAddress((void**)&kv,  g_kv);
    float* att; cudaGetSymbolAddress((void**)&att, g_att);

    const int M = B_DIM * S_DIM;   // 8192

    // 1) KV projection: only slices 1 (q==k) and 2 (v) of Wqkv are live.
    //    kv[M, 2048] = x[M,1024] @ Wqkv[:, 1024:3072] + bqkv[1024:3072]
    {
        dim3 grid(2 * C_DIM / GT, M / GT);  // (16, 64)
        sgemm_bias<<<grid, 256>>>(x, C_DIM,
                                  Wqkv + C_DIM, 3 * C_DIM,
                                  bqkv + C_DIM,
                                  kv, 2 * C_DIM,
                                  C_DIM);
    }

    // 2) Causal attention (q == k), writes att[B,S,C]
    {
        static const size_t smem = FLASH_SMEM_FLOATS * sizeof(float);
        cudaFuncSetAttribute(flash_attn, cudaFuncAttributeMaxDynamicSharedMemorySize,
                             (int)smem);
        dim3 grid(S_DIM / FBM, B_DIM * H_NUM);  // (8, 128)
        flash_attn<<<grid, 256, smem>>>(kv, att);
    }

    // 3) Output projection: out[M,1024] = att @ Wproj + bproj
    {
        dim3 grid(C_DIM / GT, M / GT);  // (8, 64)
        sgemm_bias<<<grid, 256>>>(att, C_DIM,
                                  Wproj, C_DIM,
                                  bproj,
                                  out, C_DIM,
                                  C_DIM);
    }
}

// round 8
// speedup vs baseline: 2.6974x; 2.6974x over previous
#include <cuda_runtime.h>
#include <cstdint>

// Problem constants
#define B_DIM 8
#define S_DIM 1024
#define C_DIM 1024
#define H_NUM 16
#define HD    64

// Scratch (allocation-free rule: __device__ globals)
__device__ float g_kv [(size_t)B_DIM * S_DIM * 2 * C_DIM];
__device__ float g_att[(size_t)B_DIM * S_DIM * C_DIM];

// ---------------------------------------------------------------------------
// Shared helpers
// ---------------------------------------------------------------------------
__device__ __forceinline__ uint32_t f2tf32(float f) {
    uint32_t r;
    asm("cvt.rna.tf32.f32 %0, %1;" : "=r"(r) : "f"(f));
    return r;
}
__device__ __forceinline__ float f2tf32f(float f) {
    return __uint_as_float(f2tf32(f));
}

__device__ __forceinline__ void mma_tf32(float& c0, float& c1, float& c2, float& c3,
                                         uint32_t a0, uint32_t a1, uint32_t a2, uint32_t a3,
                                         uint32_t b0, uint32_t b1) {
    asm volatile(
        "mma.sync.aligned.m16n8k8.row.col.f32.tf32.tf32.f32 "
        "{%0,%1,%2,%3}, {%4,%5,%6,%7}, {%8,%9}, {%0,%1,%2,%3};"
        : "+f"(c0), "+f"(c1), "+f"(c2), "+f"(c3)
        : "r"(a0), "r"(a1), "r"(a2), "r"(a3), "r"(b0), "r"(b1));
}

__device__ __forceinline__ void cp16(uint32_t smem_dst, const void* gsrc) {
    asm volatile("cp.async.cg.shared.global [%0], [%1], 16;\n"
                 :: "r"(smem_dst), "l"(gsrc));
}

// ---------------------------------------------------------------------------
// TF32 tensor-core GEMM: C[M,N] = A[M,K] @ B[K,N] + bias[N]
// 128x128 tile, BK=32, 256 threads (8 warps, 2x4), warp tile 64x32.
// mma.sync m16n8k8 tf32, fp32 accumulate. cp.async 2-stage pipeline.
// ---------------------------------------------------------------------------
#define GEMM_BM 128
#define GEMM_BN 128
#define GEMM_BK 32
#define AS_STRIDE 36              // floats; (4r+c)%32 distinct -> conflict-free frags
#define BS_STRIDE 136             // floats; (8k+c)%32 distinct
#define AS_FLOATS (GEMM_BM * AS_STRIDE)        // 4608
#define BS_FLOATS (GEMM_BK * BS_STRIDE)        // 4352
#define STAGE_FLOATS (AS_FLOATS + BS_FLOATS)   // 8960
#define GEMM_SMEM_BYTES (2 * STAGE_FLOATS * 4) // 71680

__global__ __launch_bounds__(256, 2)
void sgemm_tc(const float* __restrict__ A, int lda,
              const float* __restrict__ B, int ldb,
              const float* __restrict__ bias,
              float* __restrict__ Cout, int ldc, int K)
{
    extern __shared__ float sm[];
    const uint32_t sm_u32 = (uint32_t)__cvta_generic_to_shared(sm);

    const int tid = threadIdx.x;
    const int bm = blockIdx.y * GEMM_BM;
    const int bn = blockIdx.x * GEMM_BN;

    const int a_row = tid >> 1;            // 0..127
    const int a_kc  = (tid & 1) * 16;      // 0 or 16
    const int b_row = tid >> 3;            // 0..31
    const int b_col = (tid & 7) * 16;      // 0..112

    const float* Ag = A + (size_t)(bm + a_row) * lda + a_kc;
    const float* Bg = B + (size_t)b_row * ldb + bn + b_col;

    const uint32_t a_dst_base = sm_u32 + (uint32_t)(a_row * AS_STRIDE + a_kc) * 4u;
    const uint32_t b_dst_base = sm_u32 + (uint32_t)(AS_FLOATS + b_row * BS_STRIDE + b_col) * 4u;

    const int KITERS = K / GEMM_BK;

    const int wid = tid >> 5, lane = tid & 31;
    const int warp_m = wid & 1, warp_n = wid >> 1;
    const int mbase = warp_m * 64;
    const int nbase = warp_n * 32;
    const int lg = lane >> 2;   // group id 0..7
    const int lk = lane & 3;    // thread-in-group 0..3

    float acc[4][4][4];
#pragma unroll
    for (int mi = 0; mi < 4; mi++)
#pragma unroll
        for (int ni = 0; ni < 4; ni++)
#pragma unroll
            for (int q = 0; q < 4; q++) acc[mi][ni][q] = 0.f;

    // ---- issue stage 0 ----
    {
#pragma unroll
        for (int q = 0; q < 4; q++)
            cp16(a_dst_base + q * 16u, Ag + q * 4);
#pragma unroll
        for (int q = 0; q < 4; q++)
            cp16(b_dst_base + q * 16u, Bg + q * 4);
        asm volatile("cp.async.commit_group;\n" ::: "memory");
    }

    for (int it = 0; it < KITERS; it++) {
        if (it + 1 < KITERS) {
            const int k0 = (it + 1) * GEMM_BK;
            const uint32_t so = (uint32_t)(((it + 1) & 1) * STAGE_FLOATS) * 4u;
#pragma unroll
            for (int q = 0; q < 4; q++)
                cp16(a_dst_base + so + q * 16u, Ag + k0 + q * 4);
#pragma unroll
            for (int q = 0; q < 4; q++)
                cp16(b_dst_base + so + q * 16u, Bg + (size_t)k0 * ldb + q * 4);
            asm volatile("cp.async.commit_group;\n" ::: "memory");
            asm volatile("cp.async.wait_group 1;\n" ::: "memory");
        } else {
            asm volatile("cp.async.wait_group 0;\n" ::: "memory");
        }
        __syncthreads();

        const float* Ab = sm + (it & 1) * STAGE_FLOATS;
        const float* Bb = Ab + AS_FLOATS;

#pragma unroll
        for (int ks = 0; ks < GEMM_BK / 8; ks++) {
            const int kb = ks * 8;
            uint32_t af[4][4], bf[4][2];
#pragma unroll
            for (int mi = 0; mi < 4; mi++) {
                const int r0 = mbase + mi * 16 + lg;
                af[mi][0] = f2tf32(Ab[r0 * AS_STRIDE + kb + lk]);
                af[mi][1] = f2tf32(Ab[(r0 + 8) * AS_STRIDE + kb + lk]);
                af[mi][2] = f2tf32(Ab[r0 * AS_STRIDE + kb + lk + 4]);
                af[mi][3] = f2tf32(Ab[(r0 + 8) * AS_STRIDE + kb + lk + 4]);
            }
#pragma unroll
            for (int ni = 0; ni < 4; ni++) {
                const int cc = nbase + ni * 8 + lg;
                bf[ni][0] = f2tf32(Bb[(kb + lk) * BS_STRIDE + cc]);
                bf[ni][1] = f2tf32(Bb[(kb + lk + 4) * BS_STRIDE + cc]);
            }
#pragma unroll
            for (int mi = 0; mi < 4; mi++)
#pragma unroll
                for (int ni = 0; ni < 4; ni++)
                    mma_tf32(acc[mi][ni][0], acc[mi][ni][1], acc[mi][ni][2], acc[mi][ni][3],
                             af[mi][0], af[mi][1], af[mi][2], af[mi][3],
                             bf[ni][0], bf[ni][1]);
        }
        __syncthreads();
    }

    // ---- epilogue with bias ----
#pragma unroll
    for (int mi = 0; mi < 4; mi++) {
        const int r0 = bm + mbase + mi * 16 + lg;
#pragma unroll
        for (int ni = 0; ni < 4; ni++) {
            const int c0 = bn + nbase + ni * 8 + lk * 2;
            const float bx = bias[c0], by = bias[c0 + 1];
            float2 o0, o1;
            o0.x = acc[mi][ni][0] + bx; o0.y = acc[mi][ni][1] + by;
            o1.x = acc[mi][ni][2] + bx; o1.y = acc[mi][ni][3] + by;
            *(float2*)(Cout + (size_t)r0 * ldc + c0)       = o0;
            *(float2*)(Cout + (size_t)(r0 + 8) * ldc + c0) = o1;
        }
    }
}

// ---------------------------------------------------------------------------
// Flash attention (tf32 tensor cores, causal, q == k).
// Block: 128 q-rows of one (b,h); 256 threads = 8 warps; warp w owns rows
// [16w, 16w+16) = one m16 fragment row-block. Per 64-col k-tile:
//   S = Q K^T via 8x8 m16n8k8 mmas, online softmax on C fragments,
//   P -> smem (tf32), O += P V via 8x8 mmas.
// Strides chosen so all fragment LDS are bank-conflict-free:
//   Q/K/P stride 68 -> banks (4*lg+lk)%32 distinct
//   V stride 72     -> banks (8*lk+lg)%32 distinct
// ---------------------------------------------------------------------------
#define FBM 128
#define FBN 64
#define QS 68
#define KSs 68
#define VSs 72
#define PSs 68
#define FLASH_SMEM_FLOATS (FBM*QS + FBN*KSs + FBN*VSs + FBM*PSs)  // 26368 -> 103KB

__global__ __launch_bounds__(256, 2)
void flash_attn_tc(const float* __restrict__ kv, float* __restrict__ att)
{
    extern __shared__ float sm[];
    float* Qs = sm;                     // [FBM][QS]
    float* Ks = Qs + FBM * QS;          // [FBN][KSs]
    float* Vs = Ks + FBN * KSs;         // [FBN][VSs]
    float* Ps = Vs + FBN * VSs;         // [FBM][PSs]

    const int qt = blockIdx.x;          // 0..7
    const int bh = blockIdx.y;          // 0..127
    const int b = bh >> 4, h = bh & 15;
    const int tid = threadIdx.x;
    const int w = tid >> 5, lane = tid & 31;
    const int lg = lane >> 2;           // 0..7
    const int lk = lane & 3;            // 0..3
    const int rowb = w * 16;            // warp's q-row base

    const int qbase = qt * FBM;
    const size_t kvrow = 2 * C_DIM;
    const size_t kvbase = (size_t)b * S_DIM * kvrow + (size_t)h * HD;

    // ---- load Q tile [128][64], tf32-converted, stride QS ----
    for (int f = tid; f < FBM * (HD / 4); f += 256) {
        const int s = f >> 4, d4 = (f & 15) * 4;
        float4 v = *(const float4*)(kv + kvbase + (size_t)(qbase + s) * kvrow + d4);
        v.x = f2tf32f(v.x); v.y = f2tf32f(v.y);
        v.z = f2tf32f(v.z); v.w = f2tf32f(v.w);
        *(float4*)&Qs[s * QS + d4] = v;
    }

    // per-thread softmax state: rows lg (idx 0) and lg+8 (idx 1)
    float m_i[2] = {-1e30f, -1e30f};
    float l_i[2] = {0.f, 0.f};
    float outAcc[8][4];
#pragma unroll
    for (int j = 0; j < 8; j++)
#pragma unroll
        for (int q = 0; q < 4; q++) outAcc[j][q] = 0.f;

    const float scale = 0.125f;   // 1/sqrt(64)
    const int ntiles = 2 * qt + 2;

    for (int kt = 0; kt < ntiles; kt++) {
        __syncthreads();
        // ---- load K,V tiles (tf32-converted once per element) ----
        for (int f = tid; f < FBN * (HD / 4); f += 256) {
            const int s = f >> 4, d4 = (f & 15) * 4;
            const float* src = kv + kvbase + (size_t)(kt * FBN + s) * kvrow;
            float4 kk = *(const float4*)(src + d4);
            kk.x = f2tf32f(kk.x); kk.y = f2tf32f(kk.y);
            kk.z = f2tf32f(kk.z); kk.w = f2tf32f(kk.w);
            *(float4*)&Ks[s * KSs + d4] = kk;
            float4 vv = *(const float4*)(src + C_DIM + d4);
            vv.x = f2tf32f(vv.x); vv.y = f2tf32f(vv.y);
            vv.z = f2tf32f(vv.z); vv.w = f2tf32f(vv.w);
            *(float4*)&Vs[s * VSs + d4] = vv;
        }
        __syncthreads();

        // ---- S = Q K^T : acc[j] covers n-cols [8j, 8j+8) ----
        float acc[8][4];
#pragma unroll
        for (int j = 0; j < 8; j++)
#pragma unroll
            for (int q = 0; q < 4; q++) acc[j][q] = 0.f;

#pragma unroll
        for (int ks = 0; ks < 8; ks++) {
            const int kb = ks * 8;
            const uint32_t a0 = __float_as_uint(Qs[(rowb + lg)     * QS + kb + lk]);
            const uint32_t a1 = __float_as_uint(Qs[(rowb + lg + 8) * QS + kb + lk]);
            const uint32_t a2 = __float_as_uint(Qs[(rowb + lg)     * QS + kb + lk + 4]);
            const uint32_t a3 = __float_as_uint(Qs[(rowb + lg + 8) * QS + kb + lk + 4]);
#pragma unroll
            for (int j = 0; j < 8; j++) {
                const uint32_t b0 = __float_as_uint(Ks[(8 * j + lg) * KSs + kb + lk]);
                const uint32_t b1 = __float_as_uint(Ks[(8 * j + lg) * KSs + kb + lk + 4]);
                mma_tf32(acc[j][0], acc[j][1], acc[j][2], acc[j][3], a0, a1, a2, a3, b0, b1);
            }
        }

        // ---- scale + causal mask ----
        const bool domask = (kt >= 2 * qt);
        const int g0 = qbase + rowb + lg;       // row of c0,c1
        const int g1 = g0 + 8;                  // row of c2,c3
        const int cbase = kt * FBN + 2 * lk;
#pragma unroll
        for (int j = 0; j < 8; j++) {
            const int c0 = cbase + 8 * j, c1 = c0 + 1;
            float v0 = acc[j][0] * scale, v1 = acc[j][1] * scale;
            float v2 = acc[j][2] * scale, v3 = acc[j][3] * scale;
            if (domask) {
                if (c0 > g0) v0 = -1e30f;
                if (c1 > g0) v1 = -1e30f;
                if (c0 > g1) v2 = -1e30f;
                if (c1 > g1) v3 = -1e30f;
            }
            acc[j][0] = v0; acc[j][1] = v1; acc[j][2] = v2; acc[j][3] = v3;
        }

        // ---- row max (reduce over lk group: lanes xor 1,2) ----
        float mt0 = -1e30f, mt1 = -1e30f;
#pragma unroll
        for (int j = 0; j < 8; j++) {
            mt0 = fmaxf(mt0, fmaxf(acc[j][0], acc[j][1]));
            mt1 = fmaxf(mt1, fmaxf(acc[j][2], acc[j][3]));
        }
        mt0 = fmaxf(mt0, __shfl_xor_sync(0xffffffffu, mt0, 1));
        mt0 = fmaxf(mt0, __shfl_xor_sync(0xffffffffu, mt0, 2));
        mt1 = fmaxf(mt1, __shfl_xor_sync(0xffffffffu, mt1, 1));
        mt1 = fmaxf(mt1, __shfl_xor_sync(0xffffffffu, mt1, 2));

        const float mn0 = fmaxf(m_i[0], mt0);
        const float mn1 = fmaxf(m_i[1], mt1);
        const float alpha0 = __expf(m_i[0] - mn0);
        const float alpha1 = __expf(m_i[1] - mn1);
        m_i[0] = mn0; m_i[1] = mn1;

        // ---- exp, partial row-sum, write P (tf32) to smem ----
        float s0 = 0.f, s1 = 0.f;
        float* p0row = &Ps[(rowb + lg) * PSs + 2 * lk];
        float* p1row = &Ps[(rowb + lg + 8) * PSs + 2 * lk];
#pragma unroll
        for (int j = 0; j < 8; j++) {
            const float p0 = __expf(acc[j][0] - mn0);
            const float p1 = __expf(acc[j][1] - mn0);
            const float p2 = __expf(acc[j][2] - mn1);
            const float p3 = __expf(acc[j][3] - mn1);
            s0 += p0 + p1; s1 += p2 + p3;
            float2 w0; w0.x = f2tf32f(p0); w0.y = f2tf32f(p1);
            float2 w1; w1.x = f2tf32f(p2); w1.y = f2tf32f(p3);
            *(float2*)(p0row + 8 * j) = w0;
            *(float2*)(p1row + 8 * j) = w1;
        }
        s0 += __shfl_xor_sync(0xffffffffu, s0, 1);
        s0 += __shfl_xor_sync(0xffffffffu, s0, 2);
        s1 += __shfl_xor_sync(0xffffffffu, s1, 1);
        s1 += __shfl_xor_sync(0xffffffffu, s1, 2);
        l_i[0] = l_i[0] * alpha0 + s0;
        l_i[1] = l_i[1] * alpha1 + s1;

        // ---- rescale running output ----
#pragma unroll
        for (int j = 0; j < 8; j++) {
            outAcc[j][0] *= alpha0; outAcc[j][1] *= alpha0;
            outAcc[j][2] *= alpha1; outAcc[j][3] *= alpha1;
        }
        __syncwarp();

        // ---- O += P V : k-dim = 64 seq cols, n-dim = 64 head dims ----
#pragma unroll
        for (int ks = 0; ks < 8; ks++) {
            const int kb = ks * 8;
            const uint32_t a0 = __float_as_uint(Ps[(rowb + lg)     * PSs + kb + lk]);
            const uint32_t a1 = __float_as_uint(Ps[(rowb + lg + 8) * PSs + kb + lk]);
            const uint32_t a2 = __float_as_uint(Ps[(rowb + lg)     * PSs + kb + lk + 4]);
            const uint32_t a3 = __float_as_uint(Ps[(rowb + lg + 8) * PSs + kb + lk + 4]);
#pragma unroll
            for (int j = 0; j < 8; j++) {
                const uint32_t b0 = __float_as_uint(Vs[(kb + lk)     * VSs + 8 * j + lg]);
                const uint32_t b1 = __float_as_uint(Vs[(kb + lk + 4) * VSs + 8 * j + lg]);
                mma_tf32(outAcc[j][0], outAcc[j][1], outAcc[j][2], outAcc[j][3],
                         a0, a1, a2, a3, b0, b1);
            }
        }
        __syncwarp();
    }

    // ---- finalize: divide by l, write att[b, s, h*64 + col] ----
    const float inv0 = 1.0f / l_i[0];
    const float inv1 = 1.0f / l_i[1];
    const int g0 = qbase + rowb + lg;
    const size_t o0 = ((size_t)b * S_DIM + g0) * C_DIM + (size_t)h * HD + 2 * lk;
    const size_t o1 = o0 + 8 * (size_t)C_DIM;   // row g0+8
#pragma unroll
    for (int j = 0; j < 8; j++) {
        float2 r0; r0.x = outAcc[j][0] * inv0; r0.y = outAcc[j][1] * inv0;
        float2 r1; r1.x = outAcc[j][2] * inv1; r1.y = outAcc[j][3] * inv1;
        *(float2*)(att + o0 + 8 * j) = r0;
        *(float2*)(att + o1 + 8 * j) = r1;
    }
}

// ---------------------------------------------------------------------------
// Launch
// ---------------------------------------------------------------------------
extern "C" void kernel_launch(void* const* d_in, const int* in_sizes, int n_in,
                              void* d_out, int out_size)
{
    (void)in_sizes; (void)n_in; (void)out_size;
    const float* x     = (const float*)d_in[0];   // [8,1024,1024]
    const float* Wqkv  = (const float*)d_in[1];   // [1024,3072]
    const float* bqkv  = (const float*)d_in[2];   // [3072]
    const float* Wproj = (const float*)d_in[3];   // [1024,1024]
    const float* bproj = (const float*)d_in[4];   // [1024]
    float* out = (float*)d_out;                   // [8,1024,1024]

    float* kv;  cudaGetSymbolAddress((void**)&kv,  g_kv);
    float* att; cudaGetSymbolAddress((void**)&att, g_att);

    const int M = B_DIM * S_DIM;   // 8192

    cudaFuncSetAttribute(sgemm_tc, cudaFuncAttributeMaxDynamicSharedMemorySize,
                         GEMM_SMEM_BYTES);

    // 1) KV projection: only slices 1 (q==k) and 2 (v) of Wqkv are live.
    {
        dim3 grid(2 * C_DIM / GEMM_BN, M / GEMM_BM);  // (16, 64)
        sgemm_tc<<<grid, 256, GEMM_SMEM_BYTES>>>(x, C_DIM,
                                                 Wqkv + C_DIM, 3 * C_DIM,
                                                 bqkv + C_DIM,
                                                 kv, 2 * C_DIM,
                                                 C_DIM);
    }

    // 2) Causal attention (q == k), tensor-core flash, writes att[B,S,C]
    {
        const size_t smem = FLASH_SMEM_FLOATS * sizeof(float);
        cudaFuncSetAttribute(flash_attn_tc, cudaFuncAttributeMaxDynamicSharedMemorySize,
                             (int)smem);
        dim3 grid(S_DIM / FBM, B_DIM * H_NUM);  // (8, 128)
        flash_attn_tc<<<grid, 256, smem>>>(kv, att);
    }

    // 3) Output projection: out[M,1024] = att @ Wproj + bproj
    {
        dim3 grid(C_DIM / GEMM_BN, M / GEMM_BM);  // (8, 64)
        sgemm_tc<<<grid, 256, GEMM_SMEM_BYTES>>>(att, C_DIM,
                                                 Wproj, C_DIM,
                                                 bproj,
                                                 out, C_DIM,
                                                 C_DIM);
    }
}